// round 5
// baseline (speedup 1.0000x reference)
#include <cuda_runtime.h>

// Problem constants
#define BSZ 4
#define CIN_ 256
#define CQK_ 128
#define NPT 4096   // H*W*D = 16*16*16

// Scratch for projections (device globals: no allocation allowed)
__device__ float g_q[BSZ * NPT * CQK_];   // [b][n][o]   8 MB
__device__ float g_k[BSZ * NPT * CQK_];   // [b][m][o]   8 MB
__device__ float g_v[BSZ * NPT * CIN_];   // [b][m][c]  16 MB

// ---------------- f32x2 packed-math helpers (sm_100+) ----------------
typedef unsigned long long u64;

__device__ __forceinline__ u64 pack2(float lo, float hi) {
    u64 r; asm("mov.b64 %0, {%1, %2};" : "=l"(r) : "f"(lo), "f"(hi)); return r;
}
__device__ __forceinline__ void unpack2(u64 v, float& lo, float& hi) {
    asm("mov.b64 {%0, %1}, %2;" : "=f"(lo), "=f"(hi) : "l"(v));
}
__device__ __forceinline__ void ffma2(u64& d, u64 a, u64 b) {
    asm("fma.rn.f32x2 %0, %1, %2, %0;" : "+l"(d) : "l"(a), "l"(b));
}
__device__ __forceinline__ void fmul2(u64& d, u64 a) {
    asm("mul.rn.f32x2 %0, %0, %1;" : "+l"(d) : "l"(a));
}

// ---------------- Projection GEMM ----------------
// out[b][n][o] = sum_c W[o][c] * X[b][c][n] + bias[o]
// Tile: 64n x 64o, K-chunks of 32. Threads 256 = 16(tn) x 16(to), 4x4 micro-tile.
template<int OUT, int DST>
__global__ __launch_bounds__(256)
void proj_kernel(const float* __restrict__ W, const float* __restrict__ bias,
                 const float* __restrict__ X)
{
    __shared__ float sX[32 * 64];   // [c][n]
    __shared__ float sW[32 * 68];   // [c][o] stride 68 (pad)

    float* out = (DST == 0) ? g_q : (DST == 1) ? g_k : g_v;

    const int tid = threadIdx.x;
    const int tn = tid >> 4, to = tid & 15;
    const int b  = blockIdx.z;
    const int n0 = blockIdx.x * 64;
    const int o0 = blockIdx.y * 64;
    const float* Xb = X + (size_t)b * CIN_ * NPT;

    u64 acc[4][2];
#pragma unroll
    for (int i = 0; i < 4; i++) { acc[i][0] = 0ull; acc[i][1] = 0ull; }

    for (int ct = 0; ct < CIN_; ct += 32) {
        // load X tile: coalesced copy (rows c, contiguous n)
#pragma unroll
        for (int r = 0; r < 8; r++) {
            int idx = tid + r * 256;
            int c = idx >> 6, n = idx & 63;
            sX[c * 64 + n] = Xb[(size_t)(ct + c) * NPT + n0 + n];
        }
        // load W tile transposed: read coalesced in c, write [c][o]
#pragma unroll
        for (int r = 0; r < 8; r++) {
            int idx = tid + r * 256;
            int o = idx >> 5, c = idx & 31;
            sW[c * 68 + o] = W[(size_t)(o0 + o) * CIN_ + ct + c];
        }
        __syncthreads();

#pragma unroll 8
        for (int c = 0; c < 32; c++) {
            float4 xf = *(const float4*)&sX[c * 64 + 4 * tn];
            ulonglong2 wf = *(const ulonglong2*)&sW[c * 68 + 4 * to];
            u64 x0 = pack2(xf.x, xf.x), x1 = pack2(xf.y, xf.y);
            u64 x2 = pack2(xf.z, xf.z), x3 = pack2(xf.w, xf.w);
            ffma2(acc[0][0], x0, wf.x); ffma2(acc[0][1], x0, wf.y);
            ffma2(acc[1][0], x1, wf.x); ffma2(acc[1][1], x1, wf.y);
            ffma2(acc[2][0], x2, wf.x); ffma2(acc[2][1], x2, wf.y);
            ffma2(acc[3][0], x3, wf.x); ffma2(acc[3][1], x3, wf.y);
        }
        __syncthreads();
    }

    float4 bv4 = *(const float4*)&bias[o0 + 4 * to];
    float* outb = out + (size_t)b * NPT * OUT;
#pragma unroll
    for (int i = 0; i < 4; i++) {
        float a0, a1, a2, a3;
        unpack2(acc[i][0], a0, a1); unpack2(acc[i][1], a2, a3);
        float4 r = make_float4(a0 + bv4.x, a1 + bv4.y, a2 + bv4.z, a3 + bv4.w);
        *(float4*)&outb[(size_t)(n0 + 4 * tn + i) * OUT + o0 + 4 * to] = r;
    }
}

// ---------------- Fused attention ----------------
// Per CTA: one batch b, 64 queries [n0, n0+64). Loop over 64-key tiles:
//   S = Q K^T (64x64, d=128), online softmax, O += P V (d_v=256).
// Thread map (256 thr): ty=tid/16 (4 query rows 4*ty..), tx=tid%16.
//   S phase: cols 4*tx..  PV phase: channels {2*tx + 32*g, +1} for g=0..7.
#define TSTR 68   // transposed smem stride (pad: 16B-aligned float4, conflict-free)

extern __shared__ __align__(16) float smem_attn[];

__global__ __launch_bounds__(256, 1)
void attn_kernel(const float* __restrict__ gin,
                 const float* __restrict__ gamma_p,
                 float* __restrict__ out)
{
    float* sQT = smem_attn;               // [128][68] (kk-major)
    float* sKT = sQT + 128 * TSTR;        // [128][68]
    float* sV  = sKT + 128 * TSTR;        // [64][256]
    float* sP  = sV + 64 * 256;           // [64][68]

    const int tid = threadIdx.x;
    const int ty = tid >> 4, tx = tid & 15;
    const int b  = blockIdx.y;
    const int n0 = blockIdx.x * 64;

    const float* qb = g_q + ((size_t)b * NPT + n0) * CQK_;
    const float* kb = g_k + (size_t)b * NPT * CQK_;
    const float* vb = g_v + (size_t)b * NPT * CIN_;

    // Load Q transposed: sQT[o][n]
#pragma unroll
    for (int r = 0; r < 32; r++) {
        int idx = tid + r * 256;
        int n = idx >> 7, o = idx & 127;
        sQT[o * TSTR + n] = qb[n * CQK_ + o];
    }

    u64 o2[4][8];
#pragma unroll
    for (int i = 0; i < 4; i++)
#pragma unroll
        for (int g = 0; g < 8; g++) o2[i][g] = 0ull;

    float mrun[4], lrun[4];
#pragma unroll
    for (int i = 0; i < 4; i++) { mrun[i] = -1e30f; lrun[i] = 0.0f; }

    for (int m0 = 0; m0 < NPT; m0 += 64) {
        __syncthreads();   // previous tile's sKT/sV/sP consumers done
        // K tile transposed: sKT[o][m]
#pragma unroll
        for (int r = 0; r < 32; r++) {
            int idx = tid + r * 256;
            int m = idx >> 7, o = idx & 127;
            sKT[o * TSTR + m] = kb[(size_t)(m0 + m) * CQK_ + o];
        }
        // V tile: direct vectorized copy, sV[m][c]
        {
            const float4* vsrc = (const float4*)(vb + (size_t)m0 * CIN_);
            float4* vdst = (float4*)sV;
#pragma unroll
            for (int r = 0; r < 16; r++) vdst[tid + r * 256] = vsrc[tid + r * 256];
        }
        __syncthreads();

        // ---- S = Q K^T (4x4 per thread, f32x2 pairs along key dim) ----
        u64 s2[4][2];
#pragma unroll
        for (int i = 0; i < 4; i++) { s2[i][0] = 0ull; s2[i][1] = 0ull; }
#pragma unroll 4
        for (int kk = 0; kk < 128; kk++) {
            float4 qf = *(const float4*)&sQT[kk * TSTR + 4 * ty];
            ulonglong2 kf = *(const ulonglong2*)&sKT[kk * TSTR + 4 * tx];
            u64 q0 = pack2(qf.x, qf.x), q1 = pack2(qf.y, qf.y);
            u64 q2 = pack2(qf.z, qf.z), q3 = pack2(qf.w, qf.w);
            ffma2(s2[0][0], q0, kf.x); ffma2(s2[0][1], q0, kf.y);
            ffma2(s2[1][0], q1, kf.x); ffma2(s2[1][1], q1, kf.y);
            ffma2(s2[2][0], q2, kf.x); ffma2(s2[2][1], q2, kf.y);
            ffma2(s2[3][0], q3, kf.x); ffma2(s2[3][1], q3, kf.y);
        }

        // ---- online softmax (row reductions over 16 tx lanes) ----
#pragma unroll
        for (int i = 0; i < 4; i++) {
            float v0, v1, v2v, v3;
            unpack2(s2[i][0], v0, v1); unpack2(s2[i][1], v2v, v3);
            float mx = fmaxf(fmaxf(v0, v1), fmaxf(v2v, v3));
#pragma unroll
            for (int off = 8; off; off >>= 1)
                mx = fmaxf(mx, __shfl_xor_sync(0xffffffffu, mx, off));
            float mnew = fmaxf(mrun[i], mx);
            float f = __expf(mrun[i] - mnew);
            float p0 = __expf(v0 - mnew), p1 = __expf(v1 - mnew);
            float p2 = __expf(v2v - mnew), p3 = __expf(v3 - mnew);
            float rs = (p0 + p1) + (p2 + p3);
#pragma unroll
            for (int off = 8; off; off >>= 1)
                rs += __shfl_xor_sync(0xffffffffu, rs, off);
            lrun[i] = lrun[i] * f + rs;
            mrun[i] = mnew;
            u64 ff = pack2(f, f);
#pragma unroll
            for (int g = 0; g < 8; g++) fmul2(o2[i][g], ff);
            *(float4*)&sP[(4 * ty + i) * TSTR + 4 * tx] = make_float4(p0, p1, p2, p3);
        }
        __syncthreads();

        // ---- O += P V ----
#pragma unroll 2
        for (int mm = 0; mm < 64; mm++) {
            u64 pp[4];
#pragma unroll
            for (int i = 0; i < 4; i++) {
                float pv = sP[(4 * ty + i) * TSTR + mm];
                pp[i] = pack2(pv, pv);
            }
            const float* vrow = &sV[mm * 256 + 2 * tx];
            u64 vv[8];
#pragma unroll
            for (int g = 0; g < 8; g++) vv[g] = *(const u64*)&vrow[32 * g];
#pragma unroll
            for (int g = 0; g < 8; g++) {
                ffma2(o2[0][g], pp[0], vv[g]);
                ffma2(o2[1][g], pp[1], vv[g]);
                ffma2(o2[2][g], pp[2], vv[g]);
                ffma2(o2[3][g], pp[3], vv[g]);
            }
        }
    }

    // ---- epilogue: out[b][c][n] = gamma * O[c][n]/l[n] + g[b][c][n] ----
    const float gamma = gamma_p[0];
    const float* gb = gin + (size_t)b * CIN_ * NPT;
    float* ob = out + (size_t)b * CIN_ * NPT;
#pragma unroll
    for (int i = 0; i < 4; i++) {
        float rl = 1.0f / lrun[i];
        int n = n0 + 4 * ty + i;
#pragma unroll
        for (int g = 0; g < 8; g++) {
            float a, bval; unpack2(o2[i][g], a, bval);
            int c0 = 2 * tx + 32 * g;
            size_t i0 = (size_t)c0 * NPT + n;
            ob[i0]        = gamma * (a * rl)    + gb[i0];
            ob[i0 + NPT]  = gamma * (bval * rl) + gb[i0 + NPT];
        }
    }
}

// ---------------- launch ----------------
extern "C" void kernel_launch(void* const* d_in, const int* in_sizes, int n_in,
                              void* d_out, int out_size)
{
    const float* x     = (const float*)d_in[0];
    const float* g     = (const float*)d_in[1];
    const float* Wq    = (const float*)d_in[2];
    const float* bq    = (const float*)d_in[3];
    const float* Wk    = (const float*)d_in[4];
    const float* bk    = (const float*)d_in[5];
    const float* Wv    = (const float*)d_in[6];
    const float* bv    = (const float*)d_in[7];
    const float* gamma = (const float*)d_in[8];
    float* out = (float*)d_out;

    (void)in_sizes; (void)n_in; (void)out_size;

    const int ATTN_SMEM = (2 * 128 * TSTR + 64 * 256 + 64 * TSTR) * (int)sizeof(float);
    cudaFuncSetAttribute(attn_kernel, cudaFuncAttributeMaxDynamicSharedMemorySize, ATTN_SMEM);

    // projections
    proj_kernel<CQK_, 0><<<dim3(NPT / 64, CQK_ / 64, BSZ), 256>>>(Wq, bq, x);
    proj_kernel<CQK_, 1><<<dim3(NPT / 64, CQK_ / 64, BSZ), 256>>>(Wk, bk, g);
    proj_kernel<CIN_, 2><<<dim3(NPT / 64, CIN_ / 64, BSZ), 256>>>(Wv, bv, g);

    // fused attention + epilogue
    attn_kernel<<<dim3(NPT / 64, BSZ), 256, ATTN_SMEM>>>(g, gamma, out);
}

// round 7
// speedup vs baseline: 3.7333x; 3.7333x over previous
#include <cuda_runtime.h>
#include <cuda_bf16.h>
#include <cstdint>

#define BSZ 4
#define CIN_ 256
#define CQK_ 128
#define NPT 4096
#define KT 64            // keys per tile
#define NT 64            // tiles
#define QT 128           // queries per CTA

// bf16 scratch (device globals; no allocation allowed)
__device__ __nv_bfloat16 g_qh[BSZ * NPT * CQK_];   // [b][n][o]
__device__ __nv_bfloat16 g_ql[BSZ * NPT * CQK_];
__device__ __nv_bfloat16 g_kh[BSZ * NPT * CQK_];   // [b][m][o]
__device__ __nv_bfloat16 g_kl[BSZ * NPT * CQK_];
__device__ __nv_bfloat16 g_vh[BSZ * CIN_ * NPT];   // [b][c][m] channel-major

// ================= helpers =================
typedef unsigned long long u64;

__device__ __forceinline__ u64 pack2(float lo, float hi) {
    u64 r; asm("mov.b64 %0, {%1, %2};" : "=l"(r) : "f"(lo), "f"(hi)); return r;
}
__device__ __forceinline__ void unpack2(u64 v, float& lo, float& hi) {
    asm("mov.b64 {%0, %1}, %2;" : "=f"(lo), "=f"(hi) : "l"(v));
}
__device__ __forceinline__ void ffma2(u64& d, u64 a, u64 b) {
    asm("fma.rn.f32x2 %0, %1, %2, %0;" : "+l"(d) : "l"(a), "l"(b));
}
__device__ __forceinline__ uint32_t smem_u32(const void* p) {
    uint32_t a;
    asm("{ .reg .u64 t; cvta.to.shared.u64 t, %1; cvt.u32.u64 %0, t; }" : "=r"(a) : "l"(p));
    return a;
}
__device__ __forceinline__ void cp_async16(uint32_t dst, const void* src) {
    asm volatile("cp.async.cg.shared.global [%0], [%1], 16;" :: "r"(dst), "l"(src) : "memory");
}
#define CP_COMMIT() asm volatile("cp.async.commit_group;" ::: "memory")
#define CP_WAIT0()  asm volatile("cp.async.wait_group 0;" ::: "memory")

__device__ __forceinline__ void ldsm4(uint32_t addr, uint32_t r[4]) {
    asm volatile("ldmatrix.sync.aligned.m8n8.x4.shared.b16 {%0,%1,%2,%3}, [%4];"
        : "=r"(r[0]), "=r"(r[1]), "=r"(r[2]), "=r"(r[3]) : "r"(addr));
}
__device__ __forceinline__ void mma16816(float c[4], const uint32_t a[4],
                                         uint32_t b0, uint32_t b1) {
    asm volatile("mma.sync.aligned.m16n8k16.row.col.f32.bf16.bf16.f32 "
        "{%0,%1,%2,%3}, {%4,%5,%6,%7}, {%8,%9}, {%0,%1,%2,%3};"
        : "+f"(c[0]), "+f"(c[1]), "+f"(c[2]), "+f"(c[3])
        : "r"(a[0]), "r"(a[1]), "r"(a[2]), "r"(a[3]), "r"(b0), "r"(b1));
}

// swizzles: 16B-chunk XOR within a row (conflict-free ldmatrix + cp.async)
__device__ __forceinline__ uint32_t sw256(int r, int byte) {      // 256B rows (Q, K)
    return (uint32_t)(r * 256 + (((byte >> 4) ^ (r & 7)) << 4) + (byte & 15));
}
__device__ __forceinline__ uint32_t sw128(int r, int byte) {      // 128B rows (V, P)
    return (uint32_t)(r * 128 + (((byte >> 4) ^ (r & 7)) << 4) + (byte & 15));
}

// ================= Projection GEMM (FFMA fp32, bf16 split outputs) =================
// out[b][n][o] = sum_c W[o][c] * X[b][c][n] + bias[o]
template<int DST>
__global__ __launch_bounds__(256)
void proj_kernel(const float* __restrict__ W, const float* __restrict__ bias,
                 const float* __restrict__ X)
{
    __shared__ float sX[32 * 64];
    __shared__ float sW[32 * 68];

    const int tid = threadIdx.x;
    const int tn = tid >> 4, to = tid & 15;
    const int b  = blockIdx.z;
    const int n0 = blockIdx.x * 64;
    const int o0 = blockIdx.y * 64;
    const float* Xb = X + (size_t)b * CIN_ * NPT;

    u64 acc[4][2];
#pragma unroll
    for (int i = 0; i < 4; i++) { acc[i][0] = 0ull; acc[i][1] = 0ull; }

    for (int ct = 0; ct < CIN_; ct += 32) {
#pragma unroll
        for (int r = 0; r < 8; r++) {
            int idx = tid + r * 256;
            int c = idx >> 6, n = idx & 63;
            sX[c * 64 + n] = Xb[(size_t)(ct + c) * NPT + n0 + n];
        }
#pragma unroll
        for (int r = 0; r < 8; r++) {
            int idx = tid + r * 256;
            int o = idx >> 5, c = idx & 31;
            sW[c * 68 + o] = W[(size_t)(o0 + o) * CIN_ + ct + c];
        }
        __syncthreads();
#pragma unroll 8
        for (int c = 0; c < 32; c++) {
            float4 xf = *(const float4*)&sX[c * 64 + 4 * tn];
            ulonglong2 wf = *(const ulonglong2*)&sW[c * 68 + 4 * to];
            u64 x0 = pack2(xf.x, xf.x), x1 = pack2(xf.y, xf.y);
            u64 x2 = pack2(xf.z, xf.z), x3 = pack2(xf.w, xf.w);
            ffma2(acc[0][0], x0, wf.x); ffma2(acc[0][1], x0, wf.y);
            ffma2(acc[1][0], x1, wf.x); ffma2(acc[1][1], x1, wf.y);
            ffma2(acc[2][0], x2, wf.x); ffma2(acc[2][1], x2, wf.y);
            ffma2(acc[3][0], x3, wf.x); ffma2(acc[3][1], x3, wf.y);
        }
        __syncthreads();
    }

    float4 bv4 = *(const float4*)&bias[o0 + 4 * to];
    float v[4][4];
#pragma unroll
    for (int i = 0; i < 4; i++) {
        unpack2(acc[i][0], v[i][0], v[i][1]); unpack2(acc[i][1], v[i][2], v[i][3]);
        v[i][0] += bv4.x; v[i][1] += bv4.y; v[i][2] += bv4.z; v[i][3] += bv4.w;
    }

    if (DST < 2) {
        __nv_bfloat16* oh = (DST == 0) ? g_qh : g_kh;
        __nv_bfloat16* ol = (DST == 0) ? g_ql : g_kl;
#pragma unroll
        for (int i = 0; i < 4; i++) {
            uint32_t hp[2], lp[2];
#pragma unroll
            for (int half = 0; half < 2; half++) {
                __nv_bfloat16 h0 = __float2bfloat16_rn(v[i][2*half]);
                __nv_bfloat16 h1 = __float2bfloat16_rn(v[i][2*half+1]);
                __nv_bfloat16 l0 = __float2bfloat16_rn(v[i][2*half]   - __bfloat162float(h0));
                __nv_bfloat16 l1 = __float2bfloat16_rn(v[i][2*half+1] - __bfloat162float(h1));
                hp[half] = (uint32_t)__bfloat16_as_ushort(h0) | ((uint32_t)__bfloat16_as_ushort(h1) << 16);
                lp[half] = (uint32_t)__bfloat16_as_ushort(l0) | ((uint32_t)__bfloat16_as_ushort(l1) << 16);
            }
            size_t idx = (size_t)(b * NPT + n0 + 4 * tn + i) * CQK_ + o0 + 4 * to;
            *(uint2*)&oh[idx] = make_uint2(hp[0], hp[1]);
            *(uint2*)&ol[idx] = make_uint2(lp[0], lp[1]);
        }
    } else {
        // g_vh[b][c][m] channel-major
#pragma unroll
        for (int j = 0; j < 4; j++) {
            uint32_t p0 = (uint32_t)__bfloat16_as_ushort(__float2bfloat16_rn(v[0][j])) |
                          ((uint32_t)__bfloat16_as_ushort(__float2bfloat16_rn(v[1][j])) << 16);
            uint32_t p1 = (uint32_t)__bfloat16_as_ushort(__float2bfloat16_rn(v[2][j])) |
                          ((uint32_t)__bfloat16_as_ushort(__float2bfloat16_rn(v[3][j])) << 16);
            size_t idx = (size_t)(b * CIN_ + o0 + 4 * to + j) * NPT + n0 + 4 * tn;
            *(uint2*)&g_vh[idx] = make_uint2(p0, p1);
        }
    }
}

// ================= Fused mma.sync flash attention =================
// SMEM layout (bytes):
#define SM_QH   0u
#define SM_QL   32768u
#define SM_ST0  65536u       // stage base; stage = { Kh 16K | Kl 16K | V 32K }
#define STAGESZ 65536u
#define SM_P    196608u      // P bf16 [128][64]
#define SM_MAX  212992u      // [128][2] f32
#define SM_L    214016u      // [128][2] f32
#define SMEM_TOTAL 215040

__device__ __forceinline__ void load_stage(uint32_t sb, int stage, int m0, int tid,
    const __nv_bfloat16* kh, const __nv_bfloat16* kl, const __nv_bfloat16* vh)
{
    uint32_t stg = sb + SM_ST0 + (uint32_t)stage * STAGESZ;
#pragma unroll
    for (int i = 0; i < 8; i++) {
        int c = tid + i * 512;
        if (c < 2048) {
            int cc = c & 1023;
            int r = cc >> 4, ch = cc & 15;
            const __nv_bfloat16* src = ((c < 1024) ? kh : kl) + (size_t)(m0 + r) * CQK_ + ch * 8;
            cp_async16(stg + ((c < 1024) ? 0u : 16384u) + sw256(r, ch * 16), src);
        } else {
            int cc = c - 2048;
            int r = cc >> 3, ch = cc & 7;            // r = channel
            const __nv_bfloat16* src = vh + (size_t)r * NPT + m0 + ch * 8;
            cp_async16(stg + 32768u + sw128(r, ch * 16), src);
        }
    }
}

extern __shared__ __align__(16) char smem[];

__global__ __launch_bounds__(512, 1)
void attn_tc(const float* __restrict__ gin, const float* __restrict__ gamma_p,
             float* __restrict__ out)
{
    const uint32_t sb = smem_u32(smem);
    const int tid  = threadIdx.x;
    const int lane = tid & 31, wid = tid >> 5;
    const int wq = wid & 7, wh = wid >> 3;     // query group / half (keys in S, chans in PV)
    const int g = lane >> 2, tig = lane & 3;
    const int r0 = 16 * wq;
    const int b  = blockIdx.y;
    const int n0 = blockIdx.x * QT;

    const __nv_bfloat16* qh = g_qh + (size_t)(b * NPT + n0) * CQK_;
    const __nv_bfloat16* ql = g_ql + (size_t)(b * NPT + n0) * CQK_;
    const __nv_bfloat16* kh = g_kh + (size_t)b * NPT * CQK_;
    const __nv_bfloat16* kl = g_kl + (size_t)b * NPT * CQK_;
    const __nv_bfloat16* vh = g_vh + (size_t)b * CIN_ * NPT;

    // prologue: Q (hi+lo) + stage0
#pragma unroll
    for (int i = 0; i < 8; i++) {
        int c = tid + i * 512;
        int cc = c & 2047;
        int r = cc >> 4, ch = cc & 15;
        const __nv_bfloat16* src = ((c < 2048) ? qh : ql) + (size_t)r * CQK_ + ch * 8;
        cp_async16(sb + ((c < 2048) ? SM_QH : SM_QL) + sw256(r, ch * 16), src);
    }
    load_stage(sb, 0, 0, tid, kh, kl, vh);
    CP_COMMIT();

    float accO[16][4];
#pragma unroll
    for (int j = 0; j < 16; j++)
#pragma unroll
        for (int q = 0; q < 4; q++) accO[j][q] = 0.0f;

    float lsum0 = 0.0f, lsum1 = 0.0f;
    float m0r = 0.0f, m1r = 0.0f;
    const int n0w = 32 * wh;

    for (int t = 0; t < NT; t++) {
        CP_WAIT0();
        __syncthreads();
        if (t + 1 < NT) { load_stage(sb, (t + 1) & 1, (t + 1) * KT, tid, kh, kl, vh); CP_COMMIT(); }

        const uint32_t stg = sb + SM_ST0 + (uint32_t)(t & 1) * STAGESZ;
        const uint32_t sKh = stg, sKl = stg + 16384u, sV = stg + 32768u;

        // ---- S = Qh·Kh + Ql·Kh + Qh·Kl ----
        float accS[4][4];
#pragma unroll
        for (int j = 0; j < 4; j++)
#pragma unroll
            for (int q = 0; q < 4; q++) accS[j][q] = 0.0f;

#pragma unroll
        for (int kk = 0; kk < 8; kk++) {
            uint32_t Ah[4], Al[4];
            {
                int rr = r0 + (lane & 15);
                int byte = kk * 32 + ((lane >> 4) & 1) * 16;
                ldsm4(sb + SM_QH + sw256(rr, byte), Ah);
                ldsm4(sb + SM_QL + sw256(rr, byte), Al);
            }
#pragma unroll
            for (int jp = 0; jp < 2; jp++) {
                int rr = n0w + 16 * jp + ((lane >> 4) << 3) + (lane & 7);
                int byte = kk * 32 + ((lane >> 3) & 1) * 16;
                uint32_t Bh[4], Bl[4];
                ldsm4(sKh + sw256(rr, byte), Bh);
                ldsm4(sKl + sw256(rr, byte), Bl);
                mma16816(accS[2*jp],   Ah, Bh[0], Bh[1]);
                mma16816(accS[2*jp+1], Ah, Bh[2], Bh[3]);
                mma16816(accS[2*jp],   Al, Bh[0], Bh[1]);
                mma16816(accS[2*jp+1], Al, Bh[2], Bh[3]);
                mma16816(accS[2*jp],   Ah, Bl[0], Bl[1]);
                mma16816(accS[2*jp+1], Ah, Bl[2], Bl[3]);
            }
        }

        // ---- fixed row max from tile 0 ----
        if (t == 0) {
            float mA = fmaxf(fmaxf(accS[0][0], accS[0][1]), fmaxf(accS[1][0], accS[1][1]));
            mA = fmaxf(mA, fmaxf(fmaxf(accS[2][0], accS[2][1]), fmaxf(accS[3][0], accS[3][1])));
            float mB = fmaxf(fmaxf(accS[0][2], accS[0][3]), fmaxf(accS[1][2], accS[1][3]));
            mB = fmaxf(mB, fmaxf(fmaxf(accS[2][2], accS[2][3]), fmaxf(accS[3][2], accS[3][3])));
            mA = fmaxf(mA, __shfl_xor_sync(0xffffffffu, mA, 1));
            mA = fmaxf(mA, __shfl_xor_sync(0xffffffffu, mA, 2));
            mB = fmaxf(mB, __shfl_xor_sync(0xffffffffu, mB, 1));
            mB = fmaxf(mB, __shfl_xor_sync(0xffffffffu, mB, 2));
            float* sM = (float*)(smem + SM_MAX);
            if (tig == 0) {
                sM[(r0 + g) * 2 + wh]     = mA;
                sM[(r0 + g + 8) * 2 + wh] = mB;
            }
            __syncthreads();
            m0r = fmaxf(sM[(r0 + g) * 2],     sM[(r0 + g) * 2 + 1]);
            m1r = fmaxf(sM[(r0 + g + 8) * 2], sM[(r0 + g + 8) * 2 + 1]);
        }

        // ---- softmax + P(bf16) to smem, l from rounded P ----
#pragma unroll
        for (int j = 0; j < 4; j++) {
            float e0 = __expf(accS[j][0] - m0r);
            float e1 = __expf(accS[j][1] - m0r);
            float e2 = __expf(accS[j][2] - m1r);
            float e3 = __expf(accS[j][3] - m1r);
            __nv_bfloat162 p01 = __floats2bfloat162_rn(e0, e1);
            __nv_bfloat162 p23 = __floats2bfloat162_rn(e2, e3);
            lsum0 += __bfloat162float(p01.x) + __bfloat162float(p01.y);
            lsum1 += __bfloat162float(p23.x) + __bfloat162float(p23.y);
            int kb = (n0w + 8 * j + 2 * tig) * 2;
            *(uint32_t*)(smem + SM_P + sw128(r0 + g,     kb)) = *(uint32_t*)&p01;
            *(uint32_t*)(smem + SM_P + sw128(r0 + g + 8, kb)) = *(uint32_t*)&p23;
        }
        __syncthreads();

        // ---- O += P · V  (warp: 16 rows x 128 channels) ----
#pragma unroll
        for (int kk = 0; kk < 4; kk++) {
            uint32_t Ap[4];
            {
                int rr = r0 + (lane & 15);
                int byte = kk * 32 + ((lane >> 4) & 1) * 16;
                ldsm4(sb + SM_P + sw128(rr, byte), Ap);
            }
#pragma unroll
            for (int jp = 0; jp < 8; jp++) {
                int rr = 128 * wh + 16 * jp + ((lane >> 4) << 3) + (lane & 7);
                int byte = kk * 32 + ((lane >> 3) & 1) * 16;
                uint32_t Bv[4];
                ldsm4(sV + sw128(rr, byte), Bv);
                mma16816(accO[2*jp],   Ap, Bv[0], Bv[1]);
                mma16816(accO[2*jp+1], Ap, Bv[2], Bv[3]);
            }
        }
    }

    // ---- l reduction ----
    lsum0 += __shfl_xor_sync(0xffffffffu, lsum0, 1);
    lsum0 += __shfl_xor_sync(0xffffffffu, lsum0, 2);
    lsum1 += __shfl_xor_sync(0xffffffffu, lsum1, 1);
    lsum1 += __shfl_xor_sync(0xffffffffu, lsum1, 2);
    float* sL = (float*)(smem + SM_L);
    if (tig == 0) {
        sL[(r0 + g) * 2 + wh]     = lsum0;
        sL[(r0 + g + 8) * 2 + wh] = lsum1;
    }
    __syncthreads();
    const float rl0 = 1.0f / (sL[(r0 + g) * 2]     + sL[(r0 + g) * 2 + 1]);
    const float rl1 = 1.0f / (sL[(r0 + g + 8) * 2] + sL[(r0 + g + 8) * 2 + 1]);
    const float gam = gamma_p[0];

    // ---- epilogue: smem transpose, coalesced  out = gamma*O/l + g ----
    float* sT = (float*)(smem + SM_ST0);         // [64 ch][128 q] pad-132
#pragma unroll 1
    for (int blk = 0; blk < 4; blk++) {
        if (wh == (blk >> 1)) {
#pragma unroll
            for (int jj = 0; jj < 8; jj++) {
                int j  = 8 * (blk & 1) + jj;
                int cl = 8 * jj + 2 * tig;
                sT[(cl    ) * 132 + r0 + g]     = gam * accO[j][0] * rl0;
                sT[(cl + 1) * 132 + r0 + g]     = gam * accO[j][1] * rl0;
                sT[(cl    ) * 132 + r0 + g + 8] = gam * accO[j][2] * rl1;
                sT[(cl + 1) * 132 + r0 + g + 8] = gam * accO[j][3] * rl1;
            }
        }
        __syncthreads();
#pragma unroll
        for (int it = 0; it < 16; it++) {
            int idx = tid + it * 512;
            int q = idx & 127, cl = idx >> 7;
            size_t gi = (size_t)(b * CIN_ + 64 * blk + cl) * NPT + n0 + q;
            out[gi] = sT[cl * 132 + q] + gin[gi];
        }
        __syncthreads();
    }
}

// ================= launch =================
extern "C" void kernel_launch(void* const* d_in, const int* in_sizes, int n_in,
                              void* d_out, int out_size)
{
    const float* x     = (const float*)d_in[0];
    const float* g     = (const float*)d_in[1];
    const float* Wq    = (const float*)d_in[2];
    const float* bq    = (const float*)d_in[3];
    const float* Wk    = (const float*)d_in[4];
    const float* bk    = (const float*)d_in[5];
    const float* Wv    = (const float*)d_in[6];
    const float* bv    = (const float*)d_in[7];
    const float* gamma = (const float*)d_in[8];
    float* out = (float*)d_out;
    (void)in_sizes; (void)n_in; (void)out_size;

    cudaFuncSetAttribute(attn_tc, cudaFuncAttributeMaxDynamicSharedMemorySize, SMEM_TOTAL);

    proj_kernel<0><<<dim3(NPT / 64, CQK_ / 64, BSZ), 256>>>(Wq, bq, x);
    proj_kernel<1><<<dim3(NPT / 64, CQK_ / 64, BSZ), 256>>>(Wk, bk, g);
    proj_kernel<2><<<dim3(NPT / 64, CIN_ / 64, BSZ), 256>>>(Wv, bv, g);

    attn_tc<<<dim3(NPT / QT, BSZ), 512, SMEM_TOTAL>>>(g, gamma, out);
}